// round 2
// baseline (speedup 1.0000x reference)
#include <cuda_runtime.h>

#define NC   10
#define TPB  256
#define NBLK 592   // 148 SMs x 4 CTAs -> exactly one wave

// slots 0..9  : per-class sqerr sums; slots 10..19: per-class counts
__device__ float g_partials[2 * NC * NBLK];
__device__ unsigned int g_ticket = 0;

__global__ __launch_bounds__(TPB) void myloss2_fused_kernel(
    const float* __restrict__ o,
    const float* __restrict__ t,
    const int*   __restrict__ m,
    float* __restrict__ out,
    int n)
{
    float sum[NC];
#pragma unroll
    for (int c = 0; c < NC; c++) sum[c] = 0.f;
    unsigned long long pk0 = 0, pk1 = 0;  // 12-bit packed counts, classes 0-4 / 5-9

    const int nvec = n >> 2;
    const float4* __restrict__ o4 = (const float4*)o;
    const float4* __restrict__ t4 = (const float4*)t;
    const int4*   __restrict__ m4 = (const int4*)m;
    const int stride = gridDim.x * blockDim.x;

#pragma unroll 2
    for (int i = blockIdx.x * blockDim.x + threadIdx.x; i < nvec; i += stride) {
        float4 ov = o4[i];
        float4 tv = t4[i];
        int4   mv = m4[i];

        float os[4] = {ov.x, ov.y, ov.z, ov.w};
        float ts[4] = {tv.x, tv.y, tv.z, tv.w};
        int   ms[4] = {mv.x, mv.y, mv.z, mv.w};

#pragma unroll
        for (int e = 0; e < 4; e++) {
            float d  = os[e] - ts[e];
            float sq = d * d;
            int cls  = (int)ts[e];
            cls = (ms[e] == 1) ? cls : NC;       // invalid -> dummy class 10
#pragma unroll
            for (int c = 0; c < NC; c++)
                if (cls == c) sum[c] += sq;      // @P FADD (fma pipe)
            // packed count (alu pipe); cls==10 -> bits 60..63 of pk1 (dead, harmless)
            bool hi = (cls >= 5);
            int  slot = hi ? cls - 5 : cls;
            unsigned long long inc = 1ull << (slot * 12);
            if (hi) pk1 += inc; else pk0 += inc;
        }
    }

    // scalar tail (n % 4 != 0 -- not hit for this shape, kept for safety)
    if (blockIdx.x == 0 && threadIdx.x == 0) {
        for (int i = (nvec << 2); i < n; i++) {
            float d  = o[i] - t[i];
            float sq = d * d;
            int cls  = (int)t[i];
            cls = (m[i] == 1) ? cls : NC;
#pragma unroll
            for (int c = 0; c < NC; c++)
                if (cls == c) sum[c] += sq;
            bool hi = (cls >= 5);
            int  slot = hi ? cls - 5 : cls;
            unsigned long long inc = 1ull << (slot * 12);
            if (hi) pk1 += inc; else pk0 += inc;
        }
    }

    // unpack counts to floats
    float cnt[NC];
#pragma unroll
    for (int c = 0; c < 5; c++) {
        cnt[c]     = (float)((unsigned)(pk0 >> (c * 12)) & 0xFFFu);
        cnt[c + 5] = (float)((unsigned)(pk1 >> (c * 12)) & 0xFFFu);
    }

    // warp reduce 20 values
    const unsigned full = 0xffffffffu;
#pragma unroll
    for (int c = 0; c < NC; c++) {
#pragma unroll
        for (int off = 16; off; off >>= 1) {
            sum[c] += __shfl_down_sync(full, sum[c], off);
            cnt[c] += __shfl_down_sync(full, cnt[c], off);
        }
    }

    __shared__ float sh[2 * NC][TPB / 32];
    int wid = threadIdx.x >> 5;
    int lid = threadIdx.x & 31;
    if (lid == 0) {
#pragma unroll
        for (int c = 0; c < NC; c++) {
            sh[c][wid]      = sum[c];
            sh[NC + c][wid] = cnt[c];
        }
    }
    __syncthreads();

    if (threadIdx.x < 2 * NC) {
        float a = 0.f;
#pragma unroll
        for (int w = 0; w < TPB / 32; w++) a += sh[threadIdx.x][w];
        g_partials[threadIdx.x * NBLK + blockIdx.x] = a;  // deterministic write
    }

    // ---- last-block-done finalize (threadFenceReduction pattern) ----
    __shared__ unsigned int s_is_last;
    __threadfence();
    if (threadIdx.x == 0) {
        unsigned int tk = atomicAdd(&g_ticket, 1u);
        s_is_last = (tk == (unsigned)(gridDim.x - 1)) ? 1u : 0u;
    }
    __syncthreads();
    if (!s_is_last) return;

    // 8 warps cover 20 slots; fixed read order per lane -> deterministic
    __shared__ float red[2 * NC];
    for (int slot = wid; slot < 2 * NC; slot += TPB / 32) {
        float a = 0.f;
        for (int b = lid; b < NBLK; b += 32)
            a += g_partials[slot * NBLK + b];
#pragma unroll
        for (int off = 16; off; off >>= 1)
            a += __shfl_down_sync(full, a, off);
        if (lid == 0) red[slot] = a;
    }
    __syncthreads();

    if (threadIdx.x == 0) {
        float loss = 0.f;
#pragma unroll
        for (int c = 0; c < NC; c++) {
            float s  = red[c];
            float nn = red[NC + c];
            float le = (nn > 0.f) ? s / fmaxf(nn, 1.0f) : 0.0f;
            out[1 + c]  = le;   // loss_each
            out[11 + c] = nn;   // class_n
            loss += 0.1f * le;
        }
        out[0] = loss;
        g_ticket = 0;           // reset for next graph replay
    }
}

extern "C" void kernel_launch(void* const* d_in, const int* in_sizes, int n_in,
                              void* d_out, int out_size)
{
    const float* o = (const float*)d_in[0];
    const float* t = (const float*)d_in[1];
    const int*   m = (const int*)d_in[2];
    float* out = (float*)d_out;
    int n = in_sizes[0];

    myloss2_fused_kernel<<<NBLK, TPB>>>(o, t, m, out, n);
}

// round 3
// speedup vs baseline: 2.6181x; 2.6181x over previous
#include <cuda_runtime.h>

#define NC    10
#define TPB   256
#define NBLK  1184
#define CHUNK 4      // vec4 iterations per packed-count flush (16 elems <= 63 per 6-bit slot)

// slots 0..9: per-class sqerr sums; slots 10..19: per-class counts
__device__ float g_partials[2 * NC * NBLK];
__device__ unsigned int g_ticket = 0;

// Branch-free predicated accumulate: ISETP (alu) + @P FADD (fma). No BSSY/BSYNC.
#define PSUM(c)                                                             \
    asm("{.reg .pred p; setp.eq.s32 p, %1, %2; @p add.f32 %0, %0, %3;}"     \
        : "+f"(sum[c]) : "r"(cls), "n"(c), "f"(sq))

__device__ __forceinline__ void proc_elem(float ov, float tv, int mv,
                                          float (&sum)[NC],
                                          unsigned long long& pk)
{
    float d  = ov - tv;
    float sq = d * d;
    int cls  = (int)tv;                 // targets are exact small ints
    cls = (mv == 1) ? cls : NC;         // invalid -> dummy class 10
    PSUM(0); PSUM(1); PSUM(2); PSUM(3); PSUM(4);
    PSUM(5); PSUM(6); PSUM(7); PSUM(8); PSUM(9);
    pk += 1ull << (cls * 6);            // cls==10 -> bits 60.. (carries off top, harmless)
}

__global__ __launch_bounds__(TPB) void myloss2_fused_kernel(
    const float* __restrict__ o,
    const float* __restrict__ t,
    const int*   __restrict__ m,
    float* __restrict__ out,
    int n)
{
    float sum[NC];
    float cnt[NC];
#pragma unroll
    for (int c = 0; c < NC; c++) { sum[c] = 0.f; cnt[c] = 0.f; }

    const int nvec = n >> 2;
    const float4* __restrict__ o4 = (const float4*)o;
    const float4* __restrict__ t4 = (const float4*)t;
    const int4*   __restrict__ m4 = (const int4*)m;
    const int stride = NBLK * TPB;

    int i = blockIdx.x * blockDim.x + threadIdx.x;
    while (i < nvec) {
        unsigned long long pk = 0;
#pragma unroll
        for (int u = 0; u < CHUNK; u++) {
            if (i < nvec) {
                float4 ov = o4[i];
                float4 tv = t4[i];
                int4   mv = m4[i];
                proc_elem(ov.x, tv.x, mv.x, sum, pk);
                proc_elem(ov.y, tv.y, mv.y, sum, pk);
                proc_elem(ov.z, tv.z, mv.z, sum, pk);
                proc_elem(ov.w, tv.w, mv.w, sum, pk);
            }
            i += stride;
        }
        // flush packed counts (max 16 per slot per chunk)
#pragma unroll
        for (int c = 0; c < NC; c++)
            cnt[c] += (float)((unsigned)(pk >> (c * 6)) & 63u);
    }

    // scalar tail (n % 4 != 0 -- not hit for this shape, kept for safety)
    if (blockIdx.x == 0 && threadIdx.x == 0) {
        for (int k = (nvec << 2); k < n; k++) {
            float d  = o[k] - t[k];
            float sq = d * d;
            int cls  = (int)t[k];
            cls = (m[k] == 1) ? cls : NC;
#pragma unroll
            for (int c = 0; c < NC; c++) {
                if (cls == c) { sum[c] += sq; cnt[c] += 1.0f; }
            }
        }
    }

    // warp reduce 20 values
    const unsigned full = 0xffffffffu;
#pragma unroll
    for (int c = 0; c < NC; c++) {
#pragma unroll
        for (int off = 16; off; off >>= 1) {
            sum[c] += __shfl_down_sync(full, sum[c], off);
            cnt[c] += __shfl_down_sync(full, cnt[c], off);
        }
    }

    __shared__ float sh[2 * NC][TPB / 32];
    int wid = threadIdx.x >> 5;
    int lid = threadIdx.x & 31;
    if (lid == 0) {
#pragma unroll
        for (int c = 0; c < NC; c++) {
            sh[c][wid]      = sum[c];
            sh[NC + c][wid] = cnt[c];
        }
    }
    __syncthreads();

    if (threadIdx.x < 2 * NC) {
        float a = 0.f;
#pragma unroll
        for (int w = 0; w < TPB / 32; w++) a += sh[threadIdx.x][w];
        g_partials[threadIdx.x * NBLK + blockIdx.x] = a;  // deterministic write
    }

    // ---- last-block-done fused finalize ----
    __shared__ unsigned int s_is_last;
    __threadfence();
    if (threadIdx.x == 0) {
        unsigned int tk = atomicAdd(&g_ticket, 1u);
        s_is_last = (tk == (unsigned)(gridDim.x - 1)) ? 1u : 0u;
    }
    __syncthreads();
    if (!s_is_last) return;

    __shared__ float red[2 * NC];
    for (int slot = wid; slot < 2 * NC; slot += TPB / 32) {
        float a = 0.f;
        for (int b = lid; b < NBLK; b += 32)
            a += g_partials[slot * NBLK + b];
#pragma unroll
        for (int off = 16; off; off >>= 1)
            a += __shfl_down_sync(full, a, off);
        if (lid == 0) red[slot] = a;
    }
    __syncthreads();

    if (threadIdx.x == 0) {
        float loss = 0.f;
#pragma unroll
        for (int c = 0; c < NC; c++) {
            float s  = red[c];
            float nn = red[NC + c];
            float le = (nn > 0.f) ? s / fmaxf(nn, 1.0f) : 0.0f;
            out[1 + c]  = le;   // loss_each
            out[11 + c] = nn;   // class_n
            loss += 0.1f * le;
        }
        out[0] = loss;
        g_ticket = 0;           // reset for next graph replay
    }
}

extern "C" void kernel_launch(void* const* d_in, const int* in_sizes, int n_in,
                              void* d_out, int out_size)
{
    const float* o = (const float*)d_in[0];
    const float* t = (const float*)d_in[1];
    const int*   m = (const int*)d_in[2];
    float* out = (float*)d_out;
    int n = in_sizes[0];

    myloss2_fused_kernel<<<NBLK, TPB>>>(o, t, m, out, n);
}